// round 15
// baseline (speedup 1.0000x reference)
#include <cuda_runtime.h>
#include <cstdint>

// ============================================================================
// VQ-VAE forward, fp32, packed fma.rn.f32x2, fused-im2col double-buffered GEMMs.
// B=256, HW=64, L=32, E=64, Kcodes=8192.
// ============================================================================

#define DUP2(d, s)   asm("mov.b64 %0, {%1, %1};" : "=l"(d) : "f"(s))
#define FMA2(c, a, b) asm("fma.rn.f32x2 %0, %1, %2, %0;" : "+l"(c) : "l"(a), "l"(b))
#define UNPK(lo, hi, p) asm("mov.b64 {%0, %1}, %2;" : "=f"(lo), "=f"(hi) : "l"(p))
typedef unsigned long long u64;

// ----------------------------- device scratch ------------------------------
static __device__ __align__(16) float g_h1   [256*32*32*32];
static __device__ __align__(16) float g_h2   [65536*64];
static __device__ __align__(16) float g_h3   [16384*128];
static __device__ __align__(16) float g_part [8*256*2048];
static __device__ __align__(16) float g_fc   [256*512];
static __device__ __align__(16) float g_pred [256*2048];
static __device__ __align__(16) float g_enorm[8192];
static __device__ __align__(16) float g_bs   [8192*64];
static __device__ __align__(16) int   g_bi   [8192*64];
static __device__ __align__(16) int   g_cls  [8192];
static __device__ __align__(16) float g_dec  [8192*64];
static __device__ __align__(16) float g_dfc  [256*512];
static __device__ __align__(16) float g_w1r  [512*4096];
static __device__ __align__(16) float g_w2r  [256*2048];
static __device__ __align__(16) float g_w3r  [128*16];
static __device__ __align__(16) float g_d1   [256*4096];
static __device__ __align__(16) float g_t2   [4096*2048];
static __device__ __align__(16) float g_h2d  [256*16*16*128];

// ----------------------------- tiny prep kernels ---------------------------
__global__ void k_enorm(const float* __restrict__ emb) {
    int k = blockIdx.x * 256 + threadIdx.x;
    const float4* e = (const float4*)(emb + (size_t)k * 64);
    float s = 0.f;
    #pragma unroll
    for (int u = 0; u < 16; u++) {
        float4 v = e[u];
        s += v.x*v.x + v.y*v.y + v.z*v.z + v.w*v.w;
    }
    g_enorm[k] = s;
}
__global__ void k_prep_w1r(const float* __restrict__ w) {    // (4,4,512,256)
    int idx = blockIdx.x * 256 + threadIdx.x;
    int co = idx & 255, rs = (idx >> 8) & 15, k = idx >> 12;
    int r = rs >> 2, s = rs & 3;
    g_w1r[idx] = w[((((3-r)*4 + (3-s)) * 512 + k) * 256) + co];
}
__global__ void k_prep_w2r(const float* __restrict__ w) {    // (4,4,256,128)
    int idx = blockIdx.x * 256 + threadIdx.x;
    int co = idx & 127, rs = (idx >> 7) & 15, ci = idx >> 11;
    int r = rs >> 2, s = rs & 3;
    g_w2r[idx] = w[((((3-r)*4 + (3-s)) * 256 + ci) * 128) + co];
}
__global__ void k_prep_w3r(const float* __restrict__ w) {    // (4,4,128,1)
    int idx = blockIdx.x * 256 + threadIdx.x;
    int q = idx & 15, ci = idx >> 4;
    int r = q >> 2, s = q & 3;
    g_w3r[idx] = w[(((3-r)*4 + (3-s)) * 128 + ci)];
}

// ----------------------------- conv1 (Cin=1) -------------------------------
__global__ void __launch_bounds__(256) k_conv1(const float* __restrict__ x,
                                               const float* __restrict__ w,
                                               const float* __restrict__ b) {
    __shared__ float ws[512];
    __shared__ float bs[32];
    int t = threadIdx.x;
    ws[t] = w[t]; ws[t + 256] = w[t + 256];
    if (t < 32) bs[t] = b[t];
    __syncthreads();
    int ox = t & 31, oy = blockIdx.x * 8 + (t >> 5);
    int n = blockIdx.y;
    u64 acc[16];
    #pragma unroll
    for (int c = 0; c < 16; c++) acc[c] = *(const u64*)&bs[2*c];
    #pragma unroll
    for (int ky = 0; ky < 4; ky++) {
        int iy = 2*oy + ky - 1;
        if ((unsigned)iy >= 64u) continue;
        #pragma unroll
        for (int kx = 0; kx < 4; kx++) {
            int ix = 2*ox + kx - 1;
            if ((unsigned)ix >= 64u) continue;
            float xv = x[(n*64 + iy)*64 + ix];
            u64 xd; DUP2(xd, xv);
            const float* wp = &ws[(ky*4 + kx) * 32];
            #pragma unroll
            for (int c = 0; c < 16; c++) {
                u64 wv = *(const u64*)&wp[2*c];
                FMA2(acc[c], xd, wv);
            }
        }
    }
    float* o = &g_h1[(size_t)(((n*32) + oy)*32 + ox) * 32];
    #pragma unroll
    for (int c = 0; c < 16; c++) {
        float lo, hi; UNPK(lo, hi, acc[c]);
        o[2*c]   = fmaxf(lo, 0.f);
        o[2*c+1] = fmaxf(hi, 0.f);
    }
}

// ----------------------------- packed double-buffered SGEMM ----------------
// BM=128, BK=16, 256 threads (16x16). acc packed f32x2 along rows.
// LDR: 0 = plain row-major A; 2 = fused im2col of g_h1 (conv2); 3 = of g_h2.
// TN==8: B tile stored half-split (cols c -> half*64 + (c>>3)*4 + (c&3)) so
// inner-loop B reads are tx*4-strided LDS.128, conflict-free per phase.
template<int BN, int TN, int EPI, int LDR>
__device__ __forceinline__ void sgemm_body(
    const float* __restrict__ A, const float* __restrict__ Bm,
    const float* __restrict__ bias, float* __restrict__ C,
    int M, int N, int K, int kChunk, int biasMod)
{
    __shared__ float As[2][16*136];
    __shared__ float Bs[2][16*BN];
    const int t  = threadIdx.x;
    const int tx = t & 15, ty = t >> 4;
    const int m0 = blockIdx.y * 128;
    const int n0 = blockIdx.x * BN;
    const int kb0 = blockIdx.z * kChunk;

    float4 ra[2];
    float4 rb[BN/64];

    auto fetch = [&](int kb) {
        #pragma unroll
        for (int u = 0; u < 2; u++) {
            int lin = t + 256*u;
            int r = m0 + (lin >> 2);
            int kc = kb + ((lin & 3) << 2);
            if constexpr (LDR == 0) {
                ra[u] = *(const float4*)&A[(size_t)r * K + kc];
            } else if constexpr (LDR == 2) {
                int n = r >> 8, oy = (r >> 4) & 15, ox = r & 15;
                int tap = kc >> 5, ci = kc & 31;
                int iy = 2*oy + (tap >> 2) - 1, ix = 2*ox + (tap & 3) - 1;
                if ((unsigned)iy < 32u && (unsigned)ix < 32u)
                    ra[u] = *(const float4*)&A[((size_t)((n*32 + iy)*32 + ix) << 5) + ci];
                else ra[u] = make_float4(0.f, 0.f, 0.f, 0.f);
            } else {
                int n = r >> 6, oy = (r >> 3) & 7, ox = r & 7;
                int tap = kc >> 6, ci = kc & 63;
                int iy = 2*oy + (tap >> 2) - 1, ix = 2*ox + (tap & 3) - 1;
                if ((unsigned)iy < 16u && (unsigned)ix < 16u)
                    ra[u] = *(const float4*)&A[((size_t)((n*16 + iy)*16 + ix) << 6) + ci];
                else ra[u] = make_float4(0.f, 0.f, 0.f, 0.f);
            }
        }
        #pragma unroll
        for (int u = 0; u < BN/64; u++) {
            int lin = t + 256*u;
            int kr = lin / (BN/4), nc = (lin % (BN/4)) << 2;
            rb[u] = *(const float4*)&Bm[(size_t)(kb + kr) * N + n0 + nc];
        }
    };
    auto put = [&](int buf) {
        #pragma unroll
        for (int u = 0; u < 2; u++) {
            int lin = t + 256*u;
            int r = lin >> 2, kc = (lin & 3) << 2;
            As[buf][(kc+0)*136 + r] = ra[u].x;
            As[buf][(kc+1)*136 + r] = ra[u].y;
            As[buf][(kc+2)*136 + r] = ra[u].z;
            As[buf][(kc+3)*136 + r] = ra[u].w;
        }
        #pragma unroll
        for (int u = 0; u < BN/64; u++) {
            int lin = t + 256*u;
            int kr = lin / (BN/4), nc = (lin % (BN/4)) << 2;
            int pos;
            if constexpr (TN == 8) pos = ((nc >> 2) & 1) * 64 + ((nc >> 3) << 2);
            else                   pos = nc;
            *(float4*)&Bs[buf][kr*BN + pos] = rb[u];
        }
    };

    u64 acc[4][TN];
    #pragma unroll
    for (int i = 0; i < 4; i++)
        #pragma unroll
        for (int j = 0; j < TN; j++) acc[i][j] = 0ull;

    const int nT = kChunk >> 4;
    fetch(kb0);
    put(0);
    __syncthreads();

    for (int tI = 0; tI < nT; tI++) {
        if (tI + 1 < nT) fetch(kb0 + (tI + 1) * 16);
        const float* Ab = &As[tI & 1][0];
        const float* Bb = &Bs[tI & 1][0];
        #pragma unroll
        for (int k = 0; k < 16; k++) {
            float4 a0 = *(const float4*)&Ab[k*136 + ty*8];
            float4 a1 = *(const float4*)&Ab[k*136 + ty*8 + 4];
            u64 a2[4];
            a2[0] = ((const u64*)&a0)[0]; a2[1] = ((const u64*)&a0)[1];
            a2[2] = ((const u64*)&a1)[0]; a2[3] = ((const u64*)&a1)[1];
            u64 b2[TN];
            if constexpr (TN == 8) {
                float4 b0 = *(const float4*)&Bb[k*BN + tx*4];
                float4 b1 = *(const float4*)&Bb[k*BN + 64 + tx*4];
                DUP2(b2[0], b0.x); DUP2(b2[1], b0.y);
                DUP2(b2[2], b0.z); DUP2(b2[3], b0.w);
                DUP2(b2[4], b1.x); DUP2(b2[5], b1.y);
                DUP2(b2[6], b1.z); DUP2(b2[7], b1.w);
            } else {
                float4 b0 = *(const float4*)&Bb[k*BN + tx*4];
                DUP2(b2[0], b0.x); DUP2(b2[1], b0.y);
                DUP2(b2[2], b0.z); DUP2(b2[3], b0.w);
            }
            #pragma unroll
            for (int i = 0; i < 4; i++)
                #pragma unroll
                for (int j = 0; j < TN; j++)
                    FMA2(acc[i][j], a2[i], b2[j]);
        }
        if (tI + 1 < nT) put((tI + 1) & 1);
        __syncthreads();
    }

    if constexpr (EPI == 0) {
        #pragma unroll
        for (int i = 0; i < 4; i++) {
            int row = m0 + ty*8 + 2*i;
            #pragma unroll
            for (int j = 0; j < TN; j++) {
                int col = n0 + tx*TN + j;
                float lo, hi; UNPK(lo, hi, acc[i][j]);
                float bv = bias[col % biasMod];
                C[(size_t)row * N + col]     = fmaxf(lo + bv, 0.f);
                C[(size_t)(row+1) * N + col] = fmaxf(hi + bv, 0.f);
            }
        }
    } else {
        float* Cp = C + (size_t)blockIdx.z * M * N;
        #pragma unroll
        for (int i = 0; i < 4; i++) {
            int row = m0 + ty*8 + 2*i;
            #pragma unroll
            for (int j = 0; j < TN; j++) {
                int col = n0 + tx*TN + j;
                float lo, hi; UNPK(lo, hi, acc[i][j]);
                Cp[(size_t)row * N + col]     = lo;
                Cp[(size_t)(row+1) * N + col] = hi;
            }
        }
    }
}

__global__ void __launch_bounds__(256) k_g_conv2(const float* W, const float* b) {
    sgemm_body<64,4,0,2>(g_h1, W, b, g_h2, 65536, 64, 512, 512, 64);
}
__global__ void __launch_bounds__(256) k_g_conv3(const float* W, const float* b) {
    sgemm_body<128,8,0,3>(g_h2, W, b, g_h3, 16384, 128, 1024, 1024, 128);
}
__global__ void __launch_bounds__(256) k_g_fc(const float* W) {
    sgemm_body<64,4,1,0>(g_h3, W, nullptr, g_part, 256, 512, 8192, 1024, 0);
}
__global__ void __launch_bounds__(256) k_g_ffc(const float* W) {
    sgemm_body<128,8,1,0>(g_fc, W, nullptr, g_part, 256, 2048, 512, 128, 0);
}
__global__ void __launch_bounds__(256) k_g_dfc(const float* W) {
    sgemm_body<64,4,1,0>(g_dec, W, nullptr, g_part, 256, 512, 2048, 256, 0);
}
__global__ void __launch_bounds__(256) k_g_dc1() {
    sgemm_body<128,8,1,0>(g_dfc, g_w1r, nullptr, g_part, 256, 4096, 512, 256, 0);
}
__global__ void __launch_bounds__(256) k_g_dc2() {
    sgemm_body<128,8,1,0>(g_d1, g_w2r, nullptr, g_t2, 4096, 2048, 256, 256, 0);
}

// ----------------------------- split-K reduce ------------------------------
__device__ __forceinline__ void reduce_body(const float* __restrict__ part,
                                            const float* __restrict__ bias,
                                            float* __restrict__ out,
                                            int MN, int biasMod, int S) {
    int i = blockIdx.x * 256 + threadIdx.x;
    if (i >= MN) return;
    float s = 0.f;
    for (int k = 0; k < S; k++) s += part[(size_t)k * MN + i];
    out[i] = fmaxf(s + bias[i % biasMod], 0.f);
}
__global__ void k_red_fc (const float* b){ reduce_body(g_part, b, g_fc,   256*512,  512,  8); }
__global__ void k_red_ffc(const float* b){ reduce_body(g_part, b, g_pred, 256*2048, 2048, 4); }
__global__ void k_red_dfc(const float* b){ reduce_body(g_part, b, g_dfc,  256*512,  512,  8); }
__global__ void k_red_dc1(const float* b){ reduce_body(g_part, b, g_d1,   256*4096, 256,  2); }

// ----------------------------- VQ: argmax(2 p.e - |e|^2) -------------------
__global__ void __launch_bounds__(256) k_vq(const float* __restrict__ emb) {
    __shared__ float Ps[32 * 136];
    __shared__ float Es[32 * 136];
    __shared__ float ens[128];
    const int t  = threadIdx.x;
    const int tx = t & 15, ty = t >> 4;
    const int m0 = blockIdx.y << 7, n0 = blockIdx.x << 7;
    if (t < 128) ens[t] = g_enorm[n0 + t];

    u64 acc[4][8];
    #pragma unroll
    for (int i = 0; i < 4; i++)
        #pragma unroll
        for (int j = 0; j < 8; j++) acc[i][j] = 0ull;

    for (int ke = 0; ke < 64; ke += 32) {
        __syncthreads();
        #pragma unroll
        for (int u = 0; u < 4; u++) {
            int lin = t + 256*u;
            int r = lin >> 3, e4 = (lin & 7) << 2;
            float4 p = *(const float4*)&g_pred[(size_t)(m0 + r)*64 + ke + e4];
            Ps[(e4+0)*136 + r] = p.x; Ps[(e4+1)*136 + r] = p.y;
            Ps[(e4+2)*136 + r] = p.z; Ps[(e4+3)*136 + r] = p.w;
            int pr = ((r >> 2) & 1) * 64 + ((r >> 3) << 2) + (r & 3);
            float4 q = *(const float4*)&emb[(size_t)(n0 + r)*64 + ke + e4];
            Es[(e4+0)*136 + pr] = q.x; Es[(e4+1)*136 + pr] = q.y;
            Es[(e4+2)*136 + pr] = q.z; Es[(e4+3)*136 + pr] = q.w;
        }
        __syncthreads();
        #pragma unroll
        for (int e = 0; e < 32; e++) {
            float4 a0 = *(const float4*)&Ps[e*136 + ty*8];
            float4 a1 = *(const float4*)&Ps[e*136 + ty*8 + 4];
            u64 a2[4];
            a2[0] = ((const u64*)&a0)[0]; a2[1] = ((const u64*)&a0)[1];
            a2[2] = ((const u64*)&a1)[0]; a2[3] = ((const u64*)&a1)[1];
            float4 b0 = *(const float4*)&Es[e*136 + tx*4];
            float4 b1 = *(const float4*)&Es[e*136 + 64 + tx*4];
            u64 b2[8];
            DUP2(b2[0], b0.x); DUP2(b2[1], b0.y);
            DUP2(b2[2], b0.z); DUP2(b2[3], b0.w);
            DUP2(b2[4], b1.x); DUP2(b2[5], b1.y);
            DUP2(b2[6], b1.z); DUP2(b2[7], b1.w);
            #pragma unroll
            for (int i = 0; i < 4; i++)
                #pragma unroll
                for (int j = 0; j < 8; j++)
                    FMA2(acc[i][j], a2[i], b2[j]);
        }
    }
    __syncthreads();   // Ps/Es free for reduction overlay

    float* redS = Ps;
    int*   redI = (int*)Es;
    #pragma unroll
    for (int i = 0; i < 4; i++) {
        float bl = -3.402823466e38f, bh = -3.402823466e38f;
        int il = 0x7fffffff, ih = 0x7fffffff;
        #pragma unroll
        for (int j = 0; j < 8; j++) {
            float lo, hi; UNPK(lo, hi, acc[i][j]);
            int idx = n0 + tx*8 + j;
            float en = ens[tx*8 + j];
            float sl = 2.f*lo - en;
            float sh = 2.f*hi - en;
            if (sl > bl) { bl = sl; il = idx; }
            if (sh > bh) { bh = sh; ih = idx; }
        }
        redS[(ty*8 + 2*i)*17 + tx] = bl;   redI[(ty*8 + 2*i)*17 + tx] = il;
        redS[(ty*8 + 2*i+1)*17 + tx] = bh; redI[(ty*8 + 2*i+1)*17 + tx] = ih;
    }
    __syncthreads();
    if (t < 128) {
        float bsv = -3.402823466e38f; int biv = 0x7fffffff;
        #pragma unroll
        for (int x = 0; x < 16; x++) {
            float s = redS[t*17 + x]; int id = redI[t*17 + x];
            if (s > bsv || (s == bsv && id < biv)) { bsv = s; biv = id; }
        }
        g_bs[(size_t)(m0 + t)*64 + blockIdx.x] = bsv;
        g_bi[(size_t)(m0 + t)*64 + blockIdx.x] = biv;
    }
}

__global__ void k_vq_reduce() {
    int r = blockIdx.x * 256 + threadIdx.x;
    float bsv = -3.402823466e38f; int biv = 0x7fffffff;
    for (int x = 0; x < 64; x++) {
        float s = g_bs[(size_t)r*64 + x]; int id = g_bi[(size_t)r*64 + x];
        if (s > bsv || (s == bsv && id < biv)) { bsv = s; biv = id; }
    }
    g_cls[r] = biv;
}

__global__ void k_gather(const float* __restrict__ emb) {
    int idx = blockIdx.x * 256 + threadIdx.x;
    int r = idx >> 4, e4 = idx & 15;
    ((float4*)g_dec)[idx] = ((const float4*)(emb + (size_t)g_cls[r] * 64))[e4];
}

// ----------------------------- deconv2 scatter -----------------------------
__global__ void k_scatter2(const float* __restrict__ b2) {
    int idx = blockIdx.x * 256 + threadIdx.x;
    int c4 = idx & 511, p = idx >> 9;
    int co4 = c4 & 31, tap = c4 >> 5;
    int ry = tap >> 2, rx = tap & 3;
    int n = p >> 4, qy = (p >> 2) & 3, qx = p & 3;
    float4 v = ((const float4*)g_t2)[idx];
    int cob = co4 << 2;
    v.x = fmaxf(v.x + b2[cob+0], 0.f);
    v.y = fmaxf(v.y + b2[cob+1], 0.f);
    v.z = fmaxf(v.z + b2[cob+2], 0.f);
    v.w = fmaxf(v.w + b2[cob+3], 0.f);
    int Y = qy*4 + ry, X = qx*4 + rx;
    *(float4*)&g_h2d[((size_t)((n*16 + Y)*16 + X)) * 128 + cob] = v;
}

// ----------------------------- deconv3 + final scatter ---------------------
__global__ void __launch_bounds__(256) k_deconv3(const float* __restrict__ b3,
                                                 float* __restrict__ out) {
    __shared__ float ws[2048];
    int t = threadIdx.x;
    #pragma unroll
    for (int u = 0; u < 8; u++) ws[t + 256*u] = g_w3r[t + 256*u];
    __syncthreads();
    int p = blockIdx.x * 256 + t;
    int n = p >> 8, qy = (p >> 4) & 15, qx = p & 15;
    const float4* in = (const float4*)&g_h2d[(size_t)p * 128];
    float bias = b3[0];
    u64 acc[8];
    u64 bz; DUP2(bz, bias);
    #pragma unroll
    for (int q = 0; q < 8; q++) acc[q] = bz;
    #pragma unroll 4
    for (int c4 = 0; c4 < 32; c4++) {
        float4 v = in[c4];
        u64 vx, vy, vz, vw;
        DUP2(vx, v.x); DUP2(vy, v.y); DUP2(vz, v.z); DUP2(vw, v.w);
        const u64* w0 = (const u64*)&ws[(c4*4 + 0) * 16];
        const u64* w1 = (const u64*)&ws[(c4*4 + 1) * 16];
        const u64* w2 = (const u64*)&ws[(c4*4 + 2) * 16];
        const u64* w3 = (const u64*)&ws[(c4*4 + 3) * 16];
        #pragma unroll
        for (int q = 0; q < 8; q++) {
            FMA2(acc[q], vx, w0[q]);
            FMA2(acc[q], vy, w1[q]);
            FMA2(acc[q], vz, w2[q]);
            FMA2(acc[q], vw, w3[q]);
        }
    }
    float res[16];
    #pragma unroll
    for (int q = 0; q < 8; q++) UNPK(res[2*q], res[2*q+1], acc[q]);
    float* o = &out[((size_t)(n*64 + qy*4)) * 64 + qx*4];
    #pragma unroll
    for (int ry = 0; ry < 4; ry++)
        #pragma unroll
        for (int rx = 0; rx < 4; rx++)
            o[ry*64 + rx] = res[ry*4 + rx];
}

// ----------------------------- launch --------------------------------------
extern "C" void kernel_launch(void* const* d_in, const int* in_sizes, int n_in,
                              void* d_out, int out_size) {
    const float* x    = (const float*)d_in[0];
    const float* ew1  = (const float*)d_in[1];
    const float* eb1  = (const float*)d_in[2];
    const float* ew2  = (const float*)d_in[3];
    const float* eb2  = (const float*)d_in[4];
    const float* ew3  = (const float*)d_in[5];
    const float* eb3  = (const float*)d_in[6];
    const float* fcw  = (const float*)d_in[7];
    const float* fcb  = (const float*)d_in[8];
    const float* ffcw = (const float*)d_in[9];
    const float* ffcb = (const float*)d_in[10];
    const float* emb  = (const float*)d_in[11];
    const float* dfcw = (const float*)d_in[12];
    const float* dfcb = (const float*)d_in[13];
    const float* dw1  = (const float*)d_in[14];
    const float* db1  = (const float*)d_in[15];
    const float* dw2  = (const float*)d_in[16];
    const float* db2  = (const float*)d_in[17];
    const float* dw3  = (const float*)d_in[18];
    const float* db3  = (const float*)d_in[19];
    float* out = (float*)d_out;

    // encoder (im2col fused into GEMM A-loaders)
    k_conv1  <<<dim3(4, 256), 256>>>(x, ew1, eb1);
    k_enorm  <<<32, 256>>>(emb);
    k_g_conv2<<<dim3(1, 512, 1), 256>>>(ew2, eb2);
    k_g_conv3<<<dim3(1, 128, 1), 256>>>(ew3, eb3);

    // fc -> ffc
    k_g_fc   <<<dim3(8, 2, 8), 256>>>(fcw);
    k_red_fc <<<512, 256>>>(fcb);
    k_g_ffc  <<<dim3(16, 2, 4), 256>>>(ffcw);
    k_red_ffc<<<2048, 256>>>(ffcb);

    // vector quantize
    k_vq       <<<dim3(64, 64), 256>>>(emb);
    k_vq_reduce<<<32, 256>>>();
    k_gather   <<<512, 256>>>(emb);

    // decoder weight prep + decoder
    k_prep_w1r<<<8192, 256>>>(dw1);
    k_prep_w2r<<<2048, 256>>>(dw2);
    k_prep_w3r<<<8,    256>>>(dw3);

    k_g_dfc  <<<dim3(8, 2, 8), 256>>>(dfcw);
    k_red_dfc<<<512, 256>>>(dfcb);
    k_g_dc1  <<<dim3(32, 2, 2), 256>>>();
    k_red_dc1<<<4096, 256>>>(db1);
    k_g_dc2  <<<dim3(16, 32, 1), 256>>>();
    k_scatter2<<<8192, 256>>>(db2);
    k_deconv3 <<<256, 256>>>(db3, out);

    (void)in_sizes; (void)n_in; (void)out_size;
}

// round 16
// speedup vs baseline: 1.0011x; 1.0011x over previous
#include <cuda_runtime.h>
#include <cstdint>

// ============================================================================
// VQ-VAE forward, fp32, packed fma.rn.f32x2, fused-im2col double-buffered GEMMs.
// B=256, HW=64, L=32, E=64, Kcodes=8192.
// ============================================================================

#define DUP2(d, s)   asm("mov.b64 %0, {%1, %1};" : "=l"(d) : "f"(s))
#define FMA2(c, a, b) asm("fma.rn.f32x2 %0, %1, %2, %0;" : "+l"(c) : "l"(a), "l"(b))
#define UNPK(lo, hi, p) asm("mov.b64 {%0, %1}, %2;" : "=f"(lo), "=f"(hi) : "l"(p))
typedef unsigned long long u64;

// ----------------------------- device scratch ------------------------------
static __device__ __align__(16) float g_h1   [256*32*32*32];
static __device__ __align__(16) float g_h2   [65536*64];
static __device__ __align__(16) float g_h3   [16384*128];
static __device__ __align__(16) float g_part [8*256*2048];
static __device__ __align__(16) float g_fc   [256*512];
static __device__ __align__(16) float g_pred [256*2048];
static __device__ __align__(16) float g_enorm[8192];
static __device__ __align__(16) float g_bs   [8192*64];
static __device__ __align__(16) int   g_bi   [8192*64];
static __device__ __align__(16) int   g_cls  [8192];
static __device__ __align__(16) float g_dec  [8192*64];
static __device__ __align__(16) float g_dfc  [256*512];
static __device__ __align__(16) float g_w1r  [512*4096];
static __device__ __align__(16) float g_w2r  [256*2048];
static __device__ __align__(16) float g_w3r  [128*16];
static __device__ __align__(16) float g_d1   [256*4096];
static __device__ __align__(16) float g_t2   [4096*2048];
static __device__ __align__(16) float g_h2d  [256*16*16*128];

// ----------------------------- tiny prep kernels ---------------------------
__global__ void k_enorm(const float* __restrict__ emb) {
    int k = blockIdx.x * 256 + threadIdx.x;
    const float4* e = (const float4*)(emb + (size_t)k * 64);
    float s = 0.f;
    #pragma unroll
    for (int u = 0; u < 16; u++) {
        float4 v = e[u];
        s += v.x*v.x + v.y*v.y + v.z*v.z + v.w*v.w;
    }
    g_enorm[k] = s;
}
__global__ void k_prep_w1r(const float* __restrict__ w) {    // (4,4,512,256)
    int idx = blockIdx.x * 256 + threadIdx.x;
    int co = idx & 255, rs = (idx >> 8) & 15, k = idx >> 12;
    int r = rs >> 2, s = rs & 3;
    g_w1r[idx] = w[((((3-r)*4 + (3-s)) * 512 + k) * 256) + co];
}
__global__ void k_prep_w2r(const float* __restrict__ w) {    // (4,4,256,128)
    int idx = blockIdx.x * 256 + threadIdx.x;
    int co = idx & 127, rs = (idx >> 7) & 15, ci = idx >> 11;
    int r = rs >> 2, s = rs & 3;
    g_w2r[idx] = w[((((3-r)*4 + (3-s)) * 256 + ci) * 128) + co];
}
__global__ void k_prep_w3r(const float* __restrict__ w) {    // (4,4,128,1)
    int idx = blockIdx.x * 256 + threadIdx.x;
    int q = idx & 15, ci = idx >> 4;
    int r = q >> 2, s = q & 3;
    g_w3r[idx] = w[(((3-r)*4 + (3-s)) * 128 + ci)];
}

// ----------------------------- conv1 (Cin=1) -------------------------------
__global__ void __launch_bounds__(256) k_conv1(const float* __restrict__ x,
                                               const float* __restrict__ w,
                                               const float* __restrict__ b) {
    __shared__ float ws[512];
    __shared__ float bs[32];
    int t = threadIdx.x;
    ws[t] = w[t]; ws[t + 256] = w[t + 256];
    if (t < 32) bs[t] = b[t];
    __syncthreads();
    int ox = t & 31, oy = blockIdx.x * 8 + (t >> 5);
    int n = blockIdx.y;
    u64 acc[16];
    #pragma unroll
    for (int c = 0; c < 16; c++) acc[c] = *(const u64*)&bs[2*c];
    #pragma unroll
    for (int ky = 0; ky < 4; ky++) {
        int iy = 2*oy + ky - 1;
        if ((unsigned)iy >= 64u) continue;
        #pragma unroll
        for (int kx = 0; kx < 4; kx++) {
            int ix = 2*ox + kx - 1;
            if ((unsigned)ix >= 64u) continue;
            float xv = x[(n*64 + iy)*64 + ix];
            u64 xd; DUP2(xd, xv);
            const float* wp = &ws[(ky*4 + kx) * 32];
            #pragma unroll
            for (int c = 0; c < 16; c++) {
                u64 wv = *(const u64*)&wp[2*c];
                FMA2(acc[c], xd, wv);
            }
        }
    }
    float* o = &g_h1[(size_t)(((n*32) + oy)*32 + ox) * 32];
    #pragma unroll
    for (int c = 0; c < 16; c++) {
        float lo, hi; UNPK(lo, hi, acc[c]);
        o[2*c]   = fmaxf(lo, 0.f);
        o[2*c+1] = fmaxf(hi, 0.f);
    }
}

// ----------------------------- packed double-buffered SGEMM ----------------
// BM=128, BK=16, 256 threads (16x16). acc packed f32x2 along rows.
// LDR: 0 = plain row-major A; 2 = fused im2col of g_h1 (conv2); 3 = of g_h2.
// TN==8: B tile stored half-split (cols c -> half*64 + (c>>3)*4 + (c&3)) so
// inner-loop B reads are tx*4-strided LDS.128, conflict-free per phase.
template<int BN, int TN, int EPI, int LDR>
__device__ __forceinline__ void sgemm_body(
    const float* __restrict__ A, const float* __restrict__ Bm,
    const float* __restrict__ bias, float* __restrict__ C,
    int M, int N, int K, int kChunk, int biasMod)
{
    __shared__ float As[2][16*136];
    __shared__ float Bs[2][16*BN];
    const int t  = threadIdx.x;
    const int tx = t & 15, ty = t >> 4;
    const int m0 = blockIdx.y * 128;
    const int n0 = blockIdx.x * BN;
    const int kb0 = blockIdx.z * kChunk;

    float4 ra[2];
    float4 rb[BN/64];

    auto fetch = [&](int kb) {
        #pragma unroll
        for (int u = 0; u < 2; u++) {
            int lin = t + 256*u;
            int r = m0 + (lin >> 2);
            int kc = kb + ((lin & 3) << 2);
            if constexpr (LDR == 0) {
                ra[u] = *(const float4*)&A[(size_t)r * K + kc];
            } else if constexpr (LDR == 2) {
                int n = r >> 8, oy = (r >> 4) & 15, ox = r & 15;
                int tap = kc >> 5, ci = kc & 31;
                int iy = 2*oy + (tap >> 2) - 1, ix = 2*ox + (tap & 3) - 1;
                if ((unsigned)iy < 32u && (unsigned)ix < 32u)
                    ra[u] = *(const float4*)&A[((size_t)((n*32 + iy)*32 + ix) << 5) + ci];
                else ra[u] = make_float4(0.f, 0.f, 0.f, 0.f);
            } else {
                int n = r >> 6, oy = (r >> 3) & 7, ox = r & 7;
                int tap = kc >> 6, ci = kc & 63;
                int iy = 2*oy + (tap >> 2) - 1, ix = 2*ox + (tap & 3) - 1;
                if ((unsigned)iy < 16u && (unsigned)ix < 16u)
                    ra[u] = *(const float4*)&A[((size_t)((n*16 + iy)*16 + ix) << 6) + ci];
                else ra[u] = make_float4(0.f, 0.f, 0.f, 0.f);
            }
        }
        #pragma unroll
        for (int u = 0; u < BN/64; u++) {
            int lin = t + 256*u;
            int kr = lin / (BN/4), nc = (lin % (BN/4)) << 2;
            rb[u] = *(const float4*)&Bm[(size_t)(kb + kr) * N + n0 + nc];
        }
    };
    auto put = [&](int buf) {
        #pragma unroll
        for (int u = 0; u < 2; u++) {
            int lin = t + 256*u;
            int r = lin >> 2, kc = (lin & 3) << 2;
            As[buf][(kc+0)*136 + r] = ra[u].x;
            As[buf][(kc+1)*136 + r] = ra[u].y;
            As[buf][(kc+2)*136 + r] = ra[u].z;
            As[buf][(kc+3)*136 + r] = ra[u].w;
        }
        #pragma unroll
        for (int u = 0; u < BN/64; u++) {
            int lin = t + 256*u;
            int kr = lin / (BN/4), nc = (lin % (BN/4)) << 2;
            int pos;
            if constexpr (TN == 8) pos = ((nc >> 2) & 1) * 64 + ((nc >> 3) << 2);
            else                   pos = nc;
            *(float4*)&Bs[buf][kr*BN + pos] = rb[u];
        }
    };

    u64 acc[4][TN];
    #pragma unroll
    for (int i = 0; i < 4; i++)
        #pragma unroll
        for (int j = 0; j < TN; j++) acc[i][j] = 0ull;

    const int nT = kChunk >> 4;
    fetch(kb0);
    put(0);
    __syncthreads();

    for (int tI = 0; tI < nT; tI++) {
        if (tI + 1 < nT) fetch(kb0 + (tI + 1) * 16);
        const float* Ab = &As[tI & 1][0];
        const float* Bb = &Bs[tI & 1][0];
        #pragma unroll
        for (int k = 0; k < 16; k++) {
            float4 a0 = *(const float4*)&Ab[k*136 + ty*8];
            float4 a1 = *(const float4*)&Ab[k*136 + ty*8 + 4];
            u64 a2[4];
            a2[0] = ((const u64*)&a0)[0]; a2[1] = ((const u64*)&a0)[1];
            a2[2] = ((const u64*)&a1)[0]; a2[3] = ((const u64*)&a1)[1];
            u64 b2[TN];
            if constexpr (TN == 8) {
                float4 b0 = *(const float4*)&Bb[k*BN + tx*4];
                float4 b1 = *(const float4*)&Bb[k*BN + 64 + tx*4];
                DUP2(b2[0], b0.x); DUP2(b2[1], b0.y);
                DUP2(b2[2], b0.z); DUP2(b2[3], b0.w);
                DUP2(b2[4], b1.x); DUP2(b2[5], b1.y);
                DUP2(b2[6], b1.z); DUP2(b2[7], b1.w);
            } else {
                float4 b0 = *(const float4*)&Bb[k*BN + tx*4];
                DUP2(b2[0], b0.x); DUP2(b2[1], b0.y);
                DUP2(b2[2], b0.z); DUP2(b2[3], b0.w);
            }
            #pragma unroll
            for (int i = 0; i < 4; i++)
                #pragma unroll
                for (int j = 0; j < TN; j++)
                    FMA2(acc[i][j], a2[i], b2[j]);
        }
        if (tI + 1 < nT) put((tI + 1) & 1);
        __syncthreads();
    }

    if constexpr (EPI == 0) {
        #pragma unroll
        for (int i = 0; i < 4; i++) {
            int row = m0 + ty*8 + 2*i;
            #pragma unroll
            for (int j = 0; j < TN; j++) {
                int col = n0 + tx*TN + j;
                float lo, hi; UNPK(lo, hi, acc[i][j]);
                float bv = bias[col % biasMod];
                C[(size_t)row * N + col]     = fmaxf(lo + bv, 0.f);
                C[(size_t)(row+1) * N + col] = fmaxf(hi + bv, 0.f);
            }
        }
    } else {
        float* Cp = C + (size_t)blockIdx.z * M * N;
        #pragma unroll
        for (int i = 0; i < 4; i++) {
            int row = m0 + ty*8 + 2*i;
            #pragma unroll
            for (int j = 0; j < TN; j++) {
                int col = n0 + tx*TN + j;
                float lo, hi; UNPK(lo, hi, acc[i][j]);
                Cp[(size_t)row * N + col]     = lo;
                Cp[(size_t)(row+1) * N + col] = hi;
            }
        }
    }
}

__global__ void __launch_bounds__(256) k_g_conv2(const float* W, const float* b) {
    sgemm_body<64,4,0,2>(g_h1, W, b, g_h2, 65536, 64, 512, 512, 64);
}
__global__ void __launch_bounds__(256) k_g_conv3(const float* W, const float* b) {
    sgemm_body<128,8,0,3>(g_h2, W, b, g_h3, 16384, 128, 1024, 1024, 128);
}
__global__ void __launch_bounds__(256) k_g_fc(const float* W) {
    sgemm_body<64,4,1,0>(g_h3, W, nullptr, g_part, 256, 512, 8192, 1024, 0);
}
__global__ void __launch_bounds__(256) k_g_ffc(const float* W) {
    sgemm_body<128,8,1,0>(g_fc, W, nullptr, g_part, 256, 2048, 512, 128, 0);
}
__global__ void __launch_bounds__(256) k_g_dfc(const float* W) {
    sgemm_body<64,4,1,0>(g_dec, W, nullptr, g_part, 256, 512, 2048, 256, 0);
}
__global__ void __launch_bounds__(256) k_g_dc1() {
    sgemm_body<128,8,1,0>(g_dfc, g_w1r, nullptr, g_part, 256, 4096, 512, 256, 0);
}
__global__ void __launch_bounds__(256) k_g_dc2() {
    sgemm_body<128,8,1,0>(g_d1, g_w2r, nullptr, g_t2, 4096, 2048, 256, 256, 0);
}

// ----------------------------- split-K reduce ------------------------------
__device__ __forceinline__ void reduce_body(const float* __restrict__ part,
                                            const float* __restrict__ bias,
                                            float* __restrict__ out,
                                            int MN, int biasMod, int S) {
    int i = blockIdx.x * 256 + threadIdx.x;
    if (i >= MN) return;
    float s = 0.f;
    for (int k = 0; k < S; k++) s += part[(size_t)k * MN + i];
    out[i] = fmaxf(s + bias[i % biasMod], 0.f);
}
__global__ void k_red_fc (const float* b){ reduce_body(g_part, b, g_fc,   256*512,  512,  8); }
__global__ void k_red_ffc(const float* b){ reduce_body(g_part, b, g_pred, 256*2048, 2048, 4); }
__global__ void k_red_dfc(const float* b){ reduce_body(g_part, b, g_dfc,  256*512,  512,  8); }
__global__ void k_red_dc1(const float* b){ reduce_body(g_part, b, g_d1,   256*4096, 256,  2); }

// ----------------------------- VQ: argmax(2 p.e - |e|^2) -------------------
__global__ void __launch_bounds__(256) k_vq(const float* __restrict__ emb) {
    __shared__ float Ps[32 * 136];
    __shared__ float Es[32 * 136];
    __shared__ float ens[128];
    const int t  = threadIdx.x;
    const int tx = t & 15, ty = t >> 4;
    const int m0 = blockIdx.y << 7, n0 = blockIdx.x << 7;
    if (t < 128) ens[t] = g_enorm[n0 + t];

    u64 acc[4][8];
    #pragma unroll
    for (int i = 0; i < 4; i++)
        #pragma unroll
        for (int j = 0; j < 8; j++) acc[i][j] = 0ull;

    for (int ke = 0; ke < 64; ke += 32) {
        __syncthreads();
        #pragma unroll
        for (int u = 0; u < 4; u++) {
            int lin = t + 256*u;
            int r = lin >> 3, e4 = (lin & 7) << 2;
            float4 p = *(const float4*)&g_pred[(size_t)(m0 + r)*64 + ke + e4];
            Ps[(e4+0)*136 + r] = p.x; Ps[(e4+1)*136 + r] = p.y;
            Ps[(e4+2)*136 + r] = p.z; Ps[(e4+3)*136 + r] = p.w;
            int pr = ((r >> 2) & 1) * 64 + ((r >> 3) << 2) + (r & 3);
            float4 q = *(const float4*)&emb[(size_t)(n0 + r)*64 + ke + e4];
            Es[(e4+0)*136 + pr] = q.x; Es[(e4+1)*136 + pr] = q.y;
            Es[(e4+2)*136 + pr] = q.z; Es[(e4+3)*136 + pr] = q.w;
        }
        __syncthreads();
        #pragma unroll
        for (int e = 0; e < 32; e++) {
            float4 a0 = *(const float4*)&Ps[e*136 + ty*8];
            float4 a1 = *(const float4*)&Ps[e*136 + ty*8 + 4];
            u64 a2[4];
            a2[0] = ((const u64*)&a0)[0]; a2[1] = ((const u64*)&a0)[1];
            a2[2] = ((const u64*)&a1)[0]; a2[3] = ((const u64*)&a1)[1];
            float4 b0 = *(const float4*)&Es[e*136 + tx*4];
            float4 b1 = *(const float4*)&Es[e*136 + 64 + tx*4];
            u64 b2[8];
            DUP2(b2[0], b0.x); DUP2(b2[1], b0.y);
            DUP2(b2[2], b0.z); DUP2(b2[3], b0.w);
            DUP2(b2[4], b1.x); DUP2(b2[5], b1.y);
            DUP2(b2[6], b1.z); DUP2(b2[7], b1.w);
            #pragma unroll
            for (int i = 0; i < 4; i++)
                #pragma unroll
                for (int j = 0; j < 8; j++)
                    FMA2(acc[i][j], a2[i], b2[j]);
        }
    }
    __syncthreads();   // Ps/Es free for reduction overlay

    float* redS = Ps;
    int*   redI = (int*)Es;
    #pragma unroll
    for (int i = 0; i < 4; i++) {
        float bl = -3.402823466e38f, bh = -3.402823466e38f;
        int il = 0x7fffffff, ih = 0x7fffffff;
        #pragma unroll
        for (int j = 0; j < 8; j++) {
            float lo, hi; UNPK(lo, hi, acc[i][j]);
            int idx = n0 + tx*8 + j;
            float en = ens[tx*8 + j];
            float sl = 2.f*lo - en;
            float sh = 2.f*hi - en;
            if (sl > bl) { bl = sl; il = idx; }
            if (sh > bh) { bh = sh; ih = idx; }
        }
        redS[(ty*8 + 2*i)*17 + tx] = bl;   redI[(ty*8 + 2*i)*17 + tx] = il;
        redS[(ty*8 + 2*i+1)*17 + tx] = bh; redI[(ty*8 + 2*i+1)*17 + tx] = ih;
    }
    __syncthreads();
    if (t < 128) {
        float bsv = -3.402823466e38f; int biv = 0x7fffffff;
        #pragma unroll
        for (int x = 0; x < 16; x++) {
            float s = redS[t*17 + x]; int id = redI[t*17 + x];
            if (s > bsv || (s == bsv && id < biv)) { bsv = s; biv = id; }
        }
        g_bs[(size_t)(m0 + t)*64 + blockIdx.x] = bsv;
        g_bi[(size_t)(m0 + t)*64 + blockIdx.x] = biv;
    }
}

__global__ void k_vq_reduce() {
    int r = blockIdx.x * 256 + threadIdx.x;
    float bsv = -3.402823466e38f; int biv = 0x7fffffff;
    for (int x = 0; x < 64; x++) {
        float s = g_bs[(size_t)r*64 + x]; int id = g_bi[(size_t)r*64 + x];
        if (s > bsv || (s == bsv && id < biv)) { bsv = s; biv = id; }
    }
    g_cls[r] = biv;
}

__global__ void k_gather(const float* __restrict__ emb) {
    int idx = blockIdx.x * 256 + threadIdx.x;
    int r = idx >> 4, e4 = idx & 15;
    ((float4*)g_dec)[idx] = ((const float4*)(emb + (size_t)g_cls[r] * 64))[e4];
}

// ----------------------------- deconv2 scatter -----------------------------
__global__ void k_scatter2(const float* __restrict__ b2) {
    int idx = blockIdx.x * 256 + threadIdx.x;
    int c4 = idx & 511, p = idx >> 9;
    int co4 = c4 & 31, tap = c4 >> 5;
    int ry = tap >> 2, rx = tap & 3;
    int n = p >> 4, qy = (p >> 2) & 3, qx = p & 3;
    float4 v = ((const float4*)g_t2)[idx];
    int cob = co4 << 2;
    v.x = fmaxf(v.x + b2[cob+0], 0.f);
    v.y = fmaxf(v.y + b2[cob+1], 0.f);
    v.z = fmaxf(v.z + b2[cob+2], 0.f);
    v.w = fmaxf(v.w + b2[cob+3], 0.f);
    int Y = qy*4 + ry, X = qx*4 + rx;
    *(float4*)&g_h2d[((size_t)((n*16 + Y)*16 + X)) * 128 + cob] = v;
}

// ----------------------------- deconv3 + final scatter ---------------------
__global__ void __launch_bounds__(256) k_deconv3(const float* __restrict__ b3,
                                                 float* __restrict__ out) {
    __shared__ float ws[2048];
    int t = threadIdx.x;
    #pragma unroll
    for (int u = 0; u < 8; u++) ws[t + 256*u] = g_w3r[t + 256*u];
    __syncthreads();
    int p = blockIdx.x * 256 + t;
    int n = p >> 8, qy = (p >> 4) & 15, qx = p & 15;
    const float4* in = (const float4*)&g_h2d[(size_t)p * 128];
    float bias = b3[0];
    u64 acc[8];
    u64 bz; DUP2(bz, bias);
    #pragma unroll
    for (int q = 0; q < 8; q++) acc[q] = bz;
    #pragma unroll 4
    for (int c4 = 0; c4 < 32; c4++) {
        float4 v = in[c4];
        u64 vx, vy, vz, vw;
        DUP2(vx, v.x); DUP2(vy, v.y); DUP2(vz, v.z); DUP2(vw, v.w);
        const u64* w0 = (const u64*)&ws[(c4*4 + 0) * 16];
        const u64* w1 = (const u64*)&ws[(c4*4 + 1) * 16];
        const u64* w2 = (const u64*)&ws[(c4*4 + 2) * 16];
        const u64* w3 = (const u64*)&ws[(c4*4 + 3) * 16];
        #pragma unroll
        for (int q = 0; q < 8; q++) {
            FMA2(acc[q], vx, w0[q]);
            FMA2(acc[q], vy, w1[q]);
            FMA2(acc[q], vz, w2[q]);
            FMA2(acc[q], vw, w3[q]);
        }
    }
    float res[16];
    #pragma unroll
    for (int q = 0; q < 8; q++) UNPK(res[2*q], res[2*q+1], acc[q]);
    float* o = &out[((size_t)(n*64 + qy*4)) * 64 + qx*4];
    #pragma unroll
    for (int ry = 0; ry < 4; ry++)
        #pragma unroll
        for (int rx = 0; rx < 4; rx++)
            o[ry*64 + rx] = res[ry*4 + rx];
}

// ----------------------------- launch --------------------------------------
extern "C" void kernel_launch(void* const* d_in, const int* in_sizes, int n_in,
                              void* d_out, int out_size) {
    const float* x    = (const float*)d_in[0];
    const float* ew1  = (const float*)d_in[1];
    const float* eb1  = (const float*)d_in[2];
    const float* ew2  = (const float*)d_in[3];
    const float* eb2  = (const float*)d_in[4];
    const float* ew3  = (const float*)d_in[5];
    const float* eb3  = (const float*)d_in[6];
    const float* fcw  = (const float*)d_in[7];
    const float* fcb  = (const float*)d_in[8];
    const float* ffcw = (const float*)d_in[9];
    const float* ffcb = (const float*)d_in[10];
    const float* emb  = (const float*)d_in[11];
    const float* dfcw = (const float*)d_in[12];
    const float* dfcb = (const float*)d_in[13];
    const float* dw1  = (const float*)d_in[14];
    const float* db1  = (const float*)d_in[15];
    const float* dw2  = (const float*)d_in[16];
    const float* db2  = (const float*)d_in[17];
    const float* dw3  = (const float*)d_in[18];
    const float* db3  = (const float*)d_in[19];
    float* out = (float*)d_out;

    // encoder (im2col fused into GEMM A-loaders)
    k_conv1  <<<dim3(4, 256), 256>>>(x, ew1, eb1);
    k_enorm  <<<32, 256>>>(emb);
    k_g_conv2<<<dim3(1, 512, 1), 256>>>(ew2, eb2);
    k_g_conv3<<<dim3(1, 128, 1), 256>>>(ew3, eb3);

    // fc -> ffc
    k_g_fc   <<<dim3(8, 2, 8), 256>>>(fcw);
    k_red_fc <<<512, 256>>>(fcb);
    k_g_ffc  <<<dim3(16, 2, 4), 256>>>(ffcw);
    k_red_ffc<<<2048, 256>>>(ffcb);

    // vector quantize
    k_vq       <<<dim3(64, 64), 256>>>(emb);
    k_vq_reduce<<<32, 256>>>();
    k_gather   <<<512, 256>>>(emb);

    // decoder weight prep + decoder
    k_prep_w1r<<<8192, 256>>>(dw1);
    k_prep_w2r<<<2048, 256>>>(dw2);
    k_prep_w3r<<<8,    256>>>(dw3);

    k_g_dfc  <<<dim3(8, 2, 8), 256>>>(dfcw);
    k_red_dfc<<<512, 256>>>(dfcb);
    k_g_dc1  <<<dim3(32, 2, 2), 256>>>();
    k_red_dc1<<<4096, 256>>>(db1);
    k_g_dc2  <<<dim3(16, 32, 1), 256>>>();
    k_scatter2<<<8192, 256>>>(db2);
    k_deconv3 <<<256, 256>>>(db3, out);

    (void)in_sizes; (void)n_in; (void)out_size;
}

// round 17
// speedup vs baseline: 1.0961x; 1.0950x over previous
#include <cuda_runtime.h>
#include <cstdint>

// ============================================================================
// VQ-VAE forward, fp32, packed fma.rn.f32x2, fused-im2col double-buffered GEMMs.
// R17: all GEMMs BN=64/TN=4, __launch_bounds__(256,2) -> 2 CTAs/SM residency.
// ============================================================================

#define DUP2(d, s)   asm("mov.b64 %0, {%1, %1};" : "=l"(d) : "f"(s))
#define FMA2(c, a, b) asm("fma.rn.f32x2 %0, %1, %2, %0;" : "+l"(c) : "l"(a), "l"(b))
#define UNPK(lo, hi, p) asm("mov.b64 {%0, %1}, %2;" : "=f"(lo), "=f"(hi) : "l"(p))
typedef unsigned long long u64;

// ----------------------------- device scratch ------------------------------
static __device__ __align__(16) float g_h1   [256*32*32*32];
static __device__ __align__(16) float g_h2   [65536*64];
static __device__ __align__(16) float g_h3   [16384*128];
static __device__ __align__(16) float g_part [8*256*2048];
static __device__ __align__(16) float g_fc   [256*512];
static __device__ __align__(16) float g_pred [256*2048];
static __device__ __align__(16) float g_enorm[8192];
static __device__ __align__(16) float g_bs   [8192*64];
static __device__ __align__(16) int   g_bi   [8192*64];
static __device__ __align__(16) int   g_cls  [8192];
static __device__ __align__(16) float g_dec  [8192*64];
static __device__ __align__(16) float g_dfc  [256*512];
static __device__ __align__(16) float g_w1r  [512*4096];
static __device__ __align__(16) float g_w2r  [256*2048];
static __device__ __align__(16) float g_w3r  [128*16];
static __device__ __align__(16) float g_d1   [256*4096];
static __device__ __align__(16) float g_t2   [4096*2048];
static __device__ __align__(16) float g_h2d  [256*16*16*128];

// ----------------------------- tiny prep kernels ---------------------------
__global__ void k_enorm(const float* __restrict__ emb) {
    int k = blockIdx.x * 256 + threadIdx.x;
    const float4* e = (const float4*)(emb + (size_t)k * 64);
    float s = 0.f;
    #pragma unroll
    for (int u = 0; u < 16; u++) {
        float4 v = e[u];
        s += v.x*v.x + v.y*v.y + v.z*v.z + v.w*v.w;
    }
    g_enorm[k] = s;
}
__global__ void k_prep_w1r(const float* __restrict__ w) {    // (4,4,512,256)
    int idx = blockIdx.x * 256 + threadIdx.x;
    int co = idx & 255, rs = (idx >> 8) & 15, k = idx >> 12;
    int r = rs >> 2, s = rs & 3;
    g_w1r[idx] = w[((((3-r)*4 + (3-s)) * 512 + k) * 256) + co];
}
__global__ void k_prep_w2r(const float* __restrict__ w) {    // (4,4,256,128)
    int idx = blockIdx.x * 256 + threadIdx.x;
    int co = idx & 127, rs = (idx >> 7) & 15, ci = idx >> 11;
    int r = rs >> 2, s = rs & 3;
    g_w2r[idx] = w[((((3-r)*4 + (3-s)) * 256 + ci) * 128) + co];
}
__global__ void k_prep_w3r(const float* __restrict__ w) {    // (4,4,128,1)
    int idx = blockIdx.x * 256 + threadIdx.x;
    int q = idx & 15, ci = idx >> 4;
    int r = q >> 2, s = q & 3;
    g_w3r[idx] = w[(((3-r)*4 + (3-s)) * 128 + ci)];
}

// ----------------------------- conv1 (Cin=1) -------------------------------
__global__ void __launch_bounds__(256) k_conv1(const float* __restrict__ x,
                                               const float* __restrict__ w,
                                               const float* __restrict__ b) {
    __shared__ float ws[512];
    __shared__ float bs[32];
    int t = threadIdx.x;
    ws[t] = w[t]; ws[t + 256] = w[t + 256];
    if (t < 32) bs[t] = b[t];
    __syncthreads();
    int ox = t & 31, oy = blockIdx.x * 8 + (t >> 5);
    int n = blockIdx.y;
    u64 acc[16];
    #pragma unroll
    for (int c = 0; c < 16; c++) acc[c] = *(const u64*)&bs[2*c];
    #pragma unroll
    for (int ky = 0; ky < 4; ky++) {
        int iy = 2*oy + ky - 1;
        if ((unsigned)iy >= 64u) continue;
        #pragma unroll
        for (int kx = 0; kx < 4; kx++) {
            int ix = 2*ox + kx - 1;
            if ((unsigned)ix >= 64u) continue;
            float xv = x[(n*64 + iy)*64 + ix];
            u64 xd; DUP2(xd, xv);
            const float* wp = &ws[(ky*4 + kx) * 32];
            #pragma unroll
            for (int c = 0; c < 16; c++) {
                u64 wv = *(const u64*)&wp[2*c];
                FMA2(acc[c], xd, wv);
            }
        }
    }
    float* o = &g_h1[(size_t)(((n*32) + oy)*32 + ox) * 32];
    #pragma unroll
    for (int c = 0; c < 16; c++) {
        float lo, hi; UNPK(lo, hi, acc[c]);
        o[2*c]   = fmaxf(lo, 0.f);
        o[2*c+1] = fmaxf(hi, 0.f);
    }
}

// ----------------------------- packed double-buffered SGEMM ----------------
// BM=128, BN=64, BK=16, 256 threads (16x16), acc packed f32x2 along rows.
// LDR: 0 = plain row-major A; 2 = fused im2col of g_h1 (conv2); 3 = of g_h2.
template<int EPI, int LDR>
__device__ __forceinline__ void sgemm_body(
    const float* __restrict__ A, const float* __restrict__ Bm,
    const float* __restrict__ bias, float* __restrict__ C,
    int M, int N, int K, int kChunk, int biasMod)
{
    __shared__ float As[2][16*136];
    __shared__ float Bs[2][16*64];
    const int t  = threadIdx.x;
    const int tx = t & 15, ty = t >> 4;
    const int m0 = blockIdx.y * 128;
    const int n0 = blockIdx.x * 64;
    const int kb0 = blockIdx.z * kChunk;

    float4 ra[2];
    float4 rb;

    auto fetch = [&](int kb) {
        #pragma unroll
        for (int u = 0; u < 2; u++) {
            int lin = t + 256*u;
            int r = m0 + (lin >> 2);
            int kc = kb + ((lin & 3) << 2);
            if constexpr (LDR == 0) {
                ra[u] = *(const float4*)&A[(size_t)r * K + kc];
            } else if constexpr (LDR == 2) {
                int n = r >> 8, oy = (r >> 4) & 15, ox = r & 15;
                int tap = kc >> 5, ci = kc & 31;
                int iy = 2*oy + (tap >> 2) - 1, ix = 2*ox + (tap & 3) - 1;
                if ((unsigned)iy < 32u && (unsigned)ix < 32u)
                    ra[u] = *(const float4*)&A[((size_t)((n*32 + iy)*32 + ix) << 5) + ci];
                else ra[u] = make_float4(0.f, 0.f, 0.f, 0.f);
            } else {
                int n = r >> 6, oy = (r >> 3) & 7, ox = r & 7;
                int tap = kc >> 6, ci = kc & 63;
                int iy = 2*oy + (tap >> 2) - 1, ix = 2*ox + (tap & 3) - 1;
                if ((unsigned)iy < 16u && (unsigned)ix < 16u)
                    ra[u] = *(const float4*)&A[((size_t)((n*16 + iy)*16 + ix) << 6) + ci];
                else ra[u] = make_float4(0.f, 0.f, 0.f, 0.f);
            }
        }
        {
            int kr = t >> 4, nc = (t & 15) << 2;
            rb = *(const float4*)&Bm[(size_t)(kb + kr) * N + n0 + nc];
        }
    };
    auto put = [&](int buf) {
        #pragma unroll
        for (int u = 0; u < 2; u++) {
            int lin = t + 256*u;
            int r = lin >> 2, kc = (lin & 3) << 2;
            As[buf][(kc+0)*136 + r] = ra[u].x;
            As[buf][(kc+1)*136 + r] = ra[u].y;
            As[buf][(kc+2)*136 + r] = ra[u].z;
            As[buf][(kc+3)*136 + r] = ra[u].w;
        }
        {
            int kr = t >> 4, nc = (t & 15) << 2;
            *(float4*)&Bs[buf][kr*64 + nc] = rb;
        }
    };

    u64 acc[4][4];
    #pragma unroll
    for (int i = 0; i < 4; i++)
        #pragma unroll
        for (int j = 0; j < 4; j++) acc[i][j] = 0ull;

    const int nT = kChunk >> 4;
    fetch(kb0);
    put(0);
    __syncthreads();

    for (int tI = 0; tI < nT; tI++) {
        if (tI + 1 < nT) fetch(kb0 + (tI + 1) * 16);
        const float* Ab = &As[tI & 1][0];
        const float* Bb = &Bs[tI & 1][0];
        #pragma unroll
        for (int k = 0; k < 16; k++) {
            float4 a0 = *(const float4*)&Ab[k*136 + ty*8];
            float4 a1 = *(const float4*)&Ab[k*136 + ty*8 + 4];
            u64 a2[4];
            a2[0] = ((const u64*)&a0)[0]; a2[1] = ((const u64*)&a0)[1];
            a2[2] = ((const u64*)&a1)[0]; a2[3] = ((const u64*)&a1)[1];
            float4 b0 = *(const float4*)&Bb[k*64 + tx*4];
            u64 b2[4];
            DUP2(b2[0], b0.x); DUP2(b2[1], b0.y);
            DUP2(b2[2], b0.z); DUP2(b2[3], b0.w);
            #pragma unroll
            for (int i = 0; i < 4; i++)
                #pragma unroll
                for (int j = 0; j < 4; j++)
                    FMA2(acc[i][j], a2[i], b2[j]);
        }
        if (tI + 1 < nT) put((tI + 1) & 1);
        __syncthreads();
    }

    if constexpr (EPI == 0) {
        #pragma unroll
        for (int i = 0; i < 4; i++) {
            int row = m0 + ty*8 + 2*i;
            #pragma unroll
            for (int j = 0; j < 4; j++) {
                int col = n0 + tx*4 + j;
                float lo, hi; UNPK(lo, hi, acc[i][j]);
                float bv = bias[col % biasMod];
                C[(size_t)row * N + col]     = fmaxf(lo + bv, 0.f);
                C[(size_t)(row+1) * N + col] = fmaxf(hi + bv, 0.f);
            }
        }
    } else {
        float* Cp = C + (size_t)blockIdx.z * M * N;
        #pragma unroll
        for (int i = 0; i < 4; i++) {
            int row = m0 + ty*8 + 2*i;
            #pragma unroll
            for (int j = 0; j < 4; j++) {
                int col = n0 + tx*4 + j;
                float lo, hi; UNPK(lo, hi, acc[i][j]);
                Cp[(size_t)row * N + col]     = lo;
                Cp[(size_t)(row+1) * N + col] = hi;
            }
        }
    }
}

__global__ void __launch_bounds__(256,2) k_g_conv2(const float* W, const float* b) {
    sgemm_body<0,2>(g_h1, W, b, g_h2, 65536, 64, 512, 512, 64);
}
__global__ void __launch_bounds__(256,2) k_g_conv3(const float* W, const float* b) {
    sgemm_body<0,3>(g_h2, W, b, g_h3, 16384, 128, 1024, 1024, 128);
}
__global__ void __launch_bounds__(256,2) k_g_fc(const float* W) {
    sgemm_body<1,0>(g_h3, W, nullptr, g_part, 256, 512, 8192, 1024, 0);
}
__global__ void __launch_bounds__(256,2) k_g_ffc(const float* W) {
    sgemm_body<1,0>(g_fc, W, nullptr, g_part, 256, 2048, 512, 128, 0);
}
__global__ void __launch_bounds__(256,2) k_g_dfc(const float* W) {
    sgemm_body<1,0>(g_dec, W, nullptr, g_part, 256, 512, 2048, 256, 0);
}
__global__ void __launch_bounds__(256,2) k_g_dc1() {
    sgemm_body<1,0>(g_dfc, g_w1r, nullptr, g_part, 256, 4096, 512, 256, 0);
}
__global__ void __launch_bounds__(256,2) k_g_dc2() {
    sgemm_body<1,0>(g_d1, g_w2r, nullptr, g_t2, 4096, 2048, 256, 256, 0);
}

// ----------------------------- split-K reduce ------------------------------
__device__ __forceinline__ void reduce_body(const float* __restrict__ part,
                                            const float* __restrict__ bias,
                                            float* __restrict__ out,
                                            int MN, int biasMod, int S) {
    int i = blockIdx.x * 256 + threadIdx.x;
    if (i >= MN) return;
    float s = 0.f;
    for (int k = 0; k < S; k++) s += part[(size_t)k * MN + i];
    out[i] = fmaxf(s + bias[i % biasMod], 0.f);
}
__global__ void k_red_fc (const float* b){ reduce_body(g_part, b, g_fc,   256*512,  512,  8); }
__global__ void k_red_ffc(const float* b){ reduce_body(g_part, b, g_pred, 256*2048, 2048, 4); }
__global__ void k_red_dfc(const float* b){ reduce_body(g_part, b, g_dfc,  256*512,  512,  8); }
__global__ void k_red_dc1(const float* b){ reduce_body(g_part, b, g_d1,   256*4096, 256,  2); }

// ----------------------------- VQ: argmax(2 p.e - |e|^2) -------------------
__global__ void __launch_bounds__(256) k_vq(const float* __restrict__ emb) {
    __shared__ float Ps[32 * 136];
    __shared__ float Es[32 * 136];
    __shared__ float ens[128];
    const int t  = threadIdx.x;
    const int tx = t & 15, ty = t >> 4;
    const int m0 = blockIdx.y << 7, n0 = blockIdx.x << 7;
    if (t < 128) ens[t] = g_enorm[n0 + t];

    u64 acc[4][8];
    #pragma unroll
    for (int i = 0; i < 4; i++)
        #pragma unroll
        for (int j = 0; j < 8; j++) acc[i][j] = 0ull;

    for (int ke = 0; ke < 64; ke += 32) {
        __syncthreads();
        #pragma unroll
        for (int u = 0; u < 4; u++) {
            int lin = t + 256*u;
            int r = lin >> 3, e4 = (lin & 7) << 2;
            float4 p = *(const float4*)&g_pred[(size_t)(m0 + r)*64 + ke + e4];
            Ps[(e4+0)*136 + r] = p.x; Ps[(e4+1)*136 + r] = p.y;
            Ps[(e4+2)*136 + r] = p.z; Ps[(e4+3)*136 + r] = p.w;
            int pr = ((r >> 2) & 1) * 64 + ((r >> 3) << 2) + (r & 3);
            float4 q = *(const float4*)&emb[(size_t)(n0 + r)*64 + ke + e4];
            Es[(e4+0)*136 + pr] = q.x; Es[(e4+1)*136 + pr] = q.y;
            Es[(e4+2)*136 + pr] = q.z; Es[(e4+3)*136 + pr] = q.w;
        }
        __syncthreads();
        #pragma unroll
        for (int e = 0; e < 32; e++) {
            float4 a0 = *(const float4*)&Ps[e*136 + ty*8];
            float4 a1 = *(const float4*)&Ps[e*136 + ty*8 + 4];
            u64 a2[4];
            a2[0] = ((const u64*)&a0)[0]; a2[1] = ((const u64*)&a0)[1];
            a2[2] = ((const u64*)&a1)[0]; a2[3] = ((const u64*)&a1)[1];
            float4 b0 = *(const float4*)&Es[e*136 + tx*4];
            float4 b1 = *(const float4*)&Es[e*136 + 64 + tx*4];
            u64 b2[8];
            DUP2(b2[0], b0.x); DUP2(b2[1], b0.y);
            DUP2(b2[2], b0.z); DUP2(b2[3], b0.w);
            DUP2(b2[4], b1.x); DUP2(b2[5], b1.y);
            DUP2(b2[6], b1.z); DUP2(b2[7], b1.w);
            #pragma unroll
            for (int i = 0; i < 4; i++)
                #pragma unroll
                for (int j = 0; j < 8; j++)
                    FMA2(acc[i][j], a2[i], b2[j]);
        }
    }
    __syncthreads();   // Ps/Es free for reduction overlay

    float* redS = Ps;
    int*   redI = (int*)Es;
    #pragma unroll
    for (int i = 0; i < 4; i++) {
        float bl = -3.402823466e38f, bh = -3.402823466e38f;
        int il = 0x7fffffff, ih = 0x7fffffff;
        #pragma unroll
        for (int j = 0; j < 8; j++) {
            float lo, hi; UNPK(lo, hi, acc[i][j]);
            int idx = n0 + tx*8 + j;
            float en = ens[tx*8 + j];
            float sl = 2.f*lo - en;
            float sh = 2.f*hi - en;
            if (sl > bl) { bl = sl; il = idx; }
            if (sh > bh) { bh = sh; ih = idx; }
        }
        redS[(ty*8 + 2*i)*17 + tx] = bl;   redI[(ty*8 + 2*i)*17 + tx] = il;
        redS[(ty*8 + 2*i+1)*17 + tx] = bh; redI[(ty*8 + 2*i+1)*17 + tx] = ih;
    }
    __syncthreads();
    if (t < 128) {
        float bsv = -3.402823466e38f; int biv = 0x7fffffff;
        #pragma unroll
        for (int x = 0; x < 16; x++) {
            float s = redS[t*17 + x]; int id = redI[t*17 + x];
            if (s > bsv || (s == bsv && id < biv)) { bsv = s; biv = id; }
        }
        g_bs[(size_t)(m0 + t)*64 + blockIdx.x] = bsv;
        g_bi[(size_t)(m0 + t)*64 + blockIdx.x] = biv;
    }
}

__global__ void k_vq_reduce() {
    int r = blockIdx.x * 256 + threadIdx.x;
    float bsv = -3.402823466e38f; int biv = 0x7fffffff;
    for (int x = 0; x < 64; x++) {
        float s = g_bs[(size_t)r*64 + x]; int id = g_bi[(size_t)r*64 + x];
        if (s > bsv || (s == bsv && id < biv)) { bsv = s; biv = id; }
    }
    g_cls[r] = biv;
}

__global__ void k_gather(const float* __restrict__ emb) {
    int idx = blockIdx.x * 256 + threadIdx.x;
    int r = idx >> 4, e4 = idx & 15;
    ((float4*)g_dec)[idx] = ((const float4*)(emb + (size_t)g_cls[r] * 64))[e4];
}

// ----------------------------- deconv2 scatter -----------------------------
__global__ void k_scatter2(const float* __restrict__ b2) {
    int idx = blockIdx.x * 256 + threadIdx.x;
    int c4 = idx & 511, p = idx >> 9;
    int co4 = c4 & 31, tap = c4 >> 5;
    int ry = tap >> 2, rx = tap & 3;
    int n = p >> 4, qy = (p >> 2) & 3, qx = p & 3;
    float4 v = ((const float4*)g_t2)[idx];
    int cob = co4 << 2;
    v.x = fmaxf(v.x + b2[cob+0], 0.f);
    v.y = fmaxf(v.y + b2[cob+1], 0.f);
    v.z = fmaxf(v.z + b2[cob+2], 0.f);
    v.w = fmaxf(v.w + b2[cob+3], 0.f);
    int Y = qy*4 + ry, X = qx*4 + rx;
    *(float4*)&g_h2d[((size_t)((n*16 + Y)*16 + X)) * 128 + cob] = v;
}

// ----------------------------- deconv3 + final scatter ---------------------
__global__ void __launch_bounds__(256) k_deconv3(const float* __restrict__ b3,
                                                 float* __restrict__ out) {
    __shared__ float ws[2048];
    int t = threadIdx.x;
    #pragma unroll
    for (int u = 0; u < 8; u++) ws[t + 256*u] = g_w3r[t + 256*u];
    __syncthreads();
    int p = blockIdx.x * 256 + t;
    int n = p >> 8, qy = (p >> 4) & 15, qx = p & 15;
    const float4* in = (const float4*)&g_h2d[(size_t)p * 128];
    float bias = b3[0];
    u64 acc[8];
    u64 bz; DUP2(bz, bias);
    #pragma unroll
    for (int q = 0; q < 8; q++) acc[q] = bz;
    #pragma unroll 4
    for (int c4 = 0; c4 < 32; c4++) {
        float4 v = in[c4];
        u64 vx, vy, vz, vw;
        DUP2(vx, v.x); DUP2(vy, v.y); DUP2(vz, v.z); DUP2(vw, v.w);
        const u64* w0 = (const u64*)&ws[(c4*4 + 0) * 16];
        const u64* w1 = (const u64*)&ws[(c4*4 + 1) * 16];
        const u64* w2 = (const u64*)&ws[(c4*4 + 2) * 16];
        const u64* w3 = (const u64*)&ws[(c4*4 + 3) * 16];
        #pragma unroll
        for (int q = 0; q < 8; q++) {
            FMA2(acc[q], vx, w0[q]);
            FMA2(acc[q], vy, w1[q]);
            FMA2(acc[q], vz, w2[q]);
            FMA2(acc[q], vw, w3[q]);
        }
    }
    float res[16];
    #pragma unroll
    for (int q = 0; q < 8; q++) UNPK(res[2*q], res[2*q+1], acc[q]);
    float* o = &out[((size_t)(n*64 + qy*4)) * 64 + qx*4];
    #pragma unroll
    for (int ry = 0; ry < 4; ry++)
        #pragma unroll
        for (int rx = 0; rx < 4; rx++)
            o[ry*64 + rx] = res[ry*4 + rx];
}

// ----------------------------- launch --------------------------------------
extern "C" void kernel_launch(void* const* d_in, const int* in_sizes, int n_in,
                              void* d_out, int out_size) {
    const float* x    = (const float*)d_in[0];
    const float* ew1  = (const float*)d_in[1];
    const float* eb1  = (const float*)d_in[2];
    const float* ew2  = (const float*)d_in[3];
    const float* eb2  = (const float*)d_in[4];
    const float* ew3  = (const float*)d_in[5];
    const float* eb3  = (const float*)d_in[6];
    const float* fcw  = (const float*)d_in[7];
    const float* fcb  = (const float*)d_in[8];
    const float* ffcw = (const float*)d_in[9];
    const float* ffcb = (const float*)d_in[10];
    const float* emb  = (const float*)d_in[11];
    const float* dfcw = (const float*)d_in[12];
    const float* dfcb = (const float*)d_in[13];
    const float* dw1  = (const float*)d_in[14];
    const float* db1  = (const float*)d_in[15];
    const float* dw2  = (const float*)d_in[16];
    const float* db2  = (const float*)d_in[17];
    const float* dw3  = (const float*)d_in[18];
    const float* db3  = (const float*)d_in[19];
    float* out = (float*)d_out;

    // encoder (im2col fused into GEMM A-loaders)
    k_conv1  <<<dim3(4, 256), 256>>>(x, ew1, eb1);
    k_enorm  <<<32, 256>>>(emb);
    k_g_conv2<<<dim3(1, 512, 1), 256>>>(ew2, eb2);
    k_g_conv3<<<dim3(2, 128, 1), 256>>>(ew3, eb3);

    // fc -> ffc
    k_g_fc   <<<dim3(8, 2, 8), 256>>>(fcw);
    k_red_fc <<<512, 256>>>(fcb);
    k_g_ffc  <<<dim3(32, 2, 4), 256>>>(ffcw);
    k_red_ffc<<<2048, 256>>>(ffcb);

    // vector quantize
    k_vq       <<<dim3(64, 64), 256>>>(emb);
    k_vq_reduce<<<32, 256>>>();
    k_gather   <<<512, 256>>>(emb);

    // decoder weight prep + decoder
    k_prep_w1r<<<8192, 256>>>(dw1);
    k_prep_w2r<<<2048, 256>>>(dw2);
    k_prep_w3r<<<8,    256>>>(dw3);

    k_g_dfc  <<<dim3(8, 2, 8), 256>>>(dfcw);
    k_red_dfc<<<512, 256>>>(dfcb);
    k_g_dc1  <<<dim3(64, 2, 2), 256>>>();
    k_red_dc1<<<4096, 256>>>(db1);
    k_g_dc2  <<<dim3(32, 32, 1), 256>>>();
    k_scatter2<<<8192, 256>>>(db2);
    k_deconv3 <<<256, 256>>>(db3, out);

    (void)in_sizes; (void)n_in; (void)out_size;
}